// round 2
// baseline (speedup 1.0000x reference)
#include <cuda_runtime.h>
#include <cstdint>

// Problem constants (fixed by reference)
#define NB   8
#define HH   512
#define WW   512
#define DD   8
#define HWC  (HH * WW)          // 262144
#define NPIX (NB * HWC)         // 2097152 = 2^21
#define TPB  256
#define NBLK (NPIX / TPB)       // 8192

// smem attr row stride in words: 24 payload + 1 pad -> gcd(25,32)=1, conflict-free readback
#define ASTRIDE 25

__global__ __launch_bounds__(TPB)
void interp_kernel(const void* __restrict__ p2f_raw,
                   const float* __restrict__ bary,     // [NPIX,3]
                   const float4* __restrict__ attr,    // [N*NF][3][8] fp32 = 6 float4/face
                   float* __restrict__ out)            // [N][9][H][W]
{
    __shared__ int   s_face[TPB];
    __shared__ float s_attr[TPB * ASTRIDE];  // 25.6 KB

    const int tid  = threadIdx.x;
    const int pix  = blockIdx.x * TPB + tid;
    const int lane = tid & 31;

    // ---- dtype detection (int64 vs int32 pix_to_face), no extra kernel ----
    // Sample high-word positions restricted to the first half of the pixel range:
    // word index 2*j+1 with j < NPIX/2 is in-bounds under BOTH interpretations.
    // If int64: hi word of every element is 0 (face>=0) or 0xFFFFFFFF (-1) -> 32/32 match.
    // If int32: sampled words are arbitrary face values (-1 ~20%) -> ~6-7/32 match.
    const unsigned int* pw = (const unsigned int*)p2f_raw;
    unsigned int hi = __ldg(&pw[2 * (pix & (NPIX / 2 - 1)) + 1]);
    bool m = (hi == 0u) || (hi == 0xFFFFFFFFu);
    int cnt = __popc(__ballot_sync(0xffffffffu, m));
    bool is64 = (cnt >= 28);   // warp-uniform

    // ---- own pixel: face index + barycentrics (single-use -> evict-first) ----
    long long f;
    if (is64) f = __ldcs((const long long*)p2f_raw + pix);
    else      f = (long long)__ldcs((const int*)p2f_raw + pix);

    const float* bp = bary + (size_t)pix * 3;
    float b0 = __ldcs(bp + 0);
    float b1 = __ldcs(bp + 1);
    float b2 = __ldcs(bp + 2);

    s_face[tid] = (int)f;    // faces < 800000 fit int32; -1 preserved
    __syncthreads();

    // ---- cooperative gather: 6 lanes per face (96B contiguous), 5 faces/warp/iter ----
    {
        const int warp = tid >> 5;
        const int grp  = lane / 6;          // 0..4 usable, 5 => lanes 30,31 idle
        const int sub  = lane - grp * 6;    // 0..5: float4 index within face
        const bool active = (grp < 5);
        const int gbase = warp * 5 + grp;   // 0..39 groups per block pass
        #pragma unroll
        for (int it = 0; it < 7; ++it) {    // 7*40 = 280 >= 256 slots
            int slot = it * 40 + gbase;
            if (active && slot < TPB) {
                int face = s_face[slot];
                if (face >= 0) {
                    float4 v = __ldg(attr + (size_t)face * 6 + sub);
                    float* dst = &s_attr[slot * ASTRIDE + sub * 4];
                    dst[0] = v.x; dst[1] = v.y; dst[2] = v.z; dst[3] = v.w;
                }
            }
        }
    }
    __syncthreads();

    // ---- interpolate: o[d] = b0*A[v0,d] + b1*A[v1,d] + b2*A[v2,d] ----
    float o[DD];
    float vis;
    if (f >= 0) {
        const float* a = &s_attr[tid * ASTRIDE];
        #pragma unroll
        for (int d = 0; d < DD; d++)
            o[d] = b0 * a[d] + b1 * a[8 + d] + b2 * a[16 + d];
        vis = 1.0f;
    } else {
        #pragma unroll
        for (int d = 0; d < DD; d++) o[d] = 0.0f;
        vis = 0.0f;
    }

    // ---- output [N][9][H][W]: warp-coalesced plane-major stores, evict-first ----
    int n  = pix >> 18;            // / HWC (2^18)
    int hw = pix & (HWC - 1);
    float* ob = out + (size_t)n * (DD + 1) * HWC + hw;
    #pragma unroll
    for (int d = 0; d < DD; d++)
        __stcs(ob + (size_t)d * HWC, o[d]);
    __stcs(ob + (size_t)DD * HWC, vis);
}

extern "C" void kernel_launch(void* const* d_in, const int* in_sizes, int n_in,
                              void* d_out, int out_size) {
    const void*   p2f  = d_in[0];                    // [N,H,W,1] int32 or int64
    const float*  bary = (const float*)d_in[1];      // [N,H,W,1,3] fp32
    const float4* attr = (const float4*)d_in[2];     // [N,NF,3,8] fp32
    float*        out  = (float*)d_out;              // [N,9,H,W] fp32

    interp_kernel<<<NBLK, TPB>>>(p2f, bary, attr, out);
}

// round 3
// speedup vs baseline: 1.4374x; 1.4374x over previous
#include <cuda_runtime.h>
#include <cstdint>

// Problem constants (fixed by reference)
#define NB   8
#define HH   512
#define WW   512
#define DD   8
#define HWC  (HH * WW)          // 262144
#define NPIX (NB * HWC)         // 2097152 = 2^21
#define TPB  256
#define NBLK (NPIX / TPB)       // 8192

// smem attr row stride in words: 24 payload + 1 pad -> gcd(25,32)=1, conflict-free readback
#define ASTRIDE 25

__global__ __launch_bounds__(TPB, 5)
void interp_kernel(const void* __restrict__ p2f_raw,
                   const float* __restrict__ bary,     // [NPIX,3]
                   const float4* __restrict__ attr,    // [N*NF][3][8] fp32 = 6 float4/face
                   float* __restrict__ out)            // [N][9][H][W]
{
    __shared__ float s_attr[TPB * ASTRIDE];  // 25.6 KB

    const int tid   = threadIdx.x;
    const int pix   = blockIdx.x * TPB + tid;
    const int lane  = tid & 31;
    const int wbase = tid & ~31;             // warp's first slot in block

    // ---- dtype detection (int64 vs int32 pix_to_face), warp-uniform ----
    // High-word positions with j < NPIX/2 are in-bounds under BOTH interpretations.
    // int64: hi word is 0 or 0xFFFFFFFF for every element -> 32/32 match.
    // int32: sampled words are arbitrary face values -> ~6-7/32 match.
    const unsigned int* pw = (const unsigned int*)p2f_raw;
    unsigned int hi = __ldg(&pw[2 * (pix & (NPIX / 2 - 1)) + 1]);
    bool m = (hi == 0u) || (hi == 0xFFFFFFFFu);
    bool is64 = __popc(__ballot_sync(0xffffffffu, m)) >= 28;

    // ---- own pixel: face index + barycentrics (single-use -> evict-first) ----
    int f;
    if (is64) f = (int)__ldcs((const long long*)p2f_raw + pix);  // faces < 8e5 fit int32
    else      f = __ldcs((const int*)p2f_raw + pix);

    const float* bp = bary + (size_t)pix * 3;
    float b0 = __ldcs(bp + 0);
    float b1 = __ldcs(bp + 1);
    float b2 = __ldcs(bp + 2);

    // ---- warp-cooperative gather: 32 faces x 96B = 192 float4 = 6 full iters ----
    // iter i, lane l covers packed index p = i*32 + l: slot q = p/6, sub = p%6.
    int q   = lane / 6;
    int sub = lane - q * 6;
    int faces[6], qs[6], subs[6];
    #pragma unroll
    for (int i = 0; i < 6; i++) {
        faces[i] = __shfl_sync(0xffffffffu, f, q);
        qs[i] = q; subs[i] = sub;
        sub += 2; q += 5;                    // advance p by 32 = 5*6 + 2
        if (sub >= 6) { sub -= 6; q += 1; }
    }
    float4 v[6];
    #pragma unroll
    for (int i = 0; i < 6; i++) {
        if (faces[i] >= 0)
            v[i] = __ldg(attr + (size_t)faces[i] * 6 + subs[i]);
    }
    #pragma unroll
    for (int i = 0; i < 6; i++) {
        if (faces[i] >= 0) {
            float* dst = &s_attr[(wbase + qs[i]) * ASTRIDE + subs[i] * 4];
            dst[0] = v[i].x; dst[1] = v[i].y; dst[2] = v[i].z; dst[3] = v[i].w;
        }
    }
    __syncwarp();   // producer == consumer warp; no cross-warp coupling

    // ---- interpolate: o[d] = b0*A[v0,d] + b1*A[v1,d] + b2*A[v2,d] ----
    float o[DD];
    float vis;
    if (f >= 0) {
        const float* a = &s_attr[tid * ASTRIDE];   // stride 25: conflict-free
        #pragma unroll
        for (int d = 0; d < DD; d++)
            o[d] = b0 * a[d] + b1 * a[8 + d] + b2 * a[16 + d];
        vis = 1.0f;
    } else {
        #pragma unroll
        for (int d = 0; d < DD; d++) o[d] = 0.0f;
        vis = 0.0f;
    }

    // ---- output [N][9][H][W]: warp-coalesced plane-major stores, evict-first ----
    int n  = pix >> 18;            // / HWC (2^18)
    int hw = pix & (HWC - 1);
    float* ob = out + (size_t)n * (DD + 1) * HWC + hw;
    #pragma unroll
    for (int d = 0; d < DD; d++)
        __stcs(ob + (size_t)d * HWC, o[d]);
    __stcs(ob + (size_t)DD * HWC, vis);
}

extern "C" void kernel_launch(void* const* d_in, const int* in_sizes, int n_in,
                              void* d_out, int out_size) {
    const void*   p2f  = d_in[0];                    // [N,H,W,1] int32 or int64
    const float*  bary = (const float*)d_in[1];      // [N,H,W,1,3] fp32
    const float4* attr = (const float4*)d_in[2];     // [N,NF,3,8] fp32
    float*        out  = (float*)d_out;              // [N,9,H,W] fp32

    interp_kernel<<<NBLK, TPB>>>(p2f, bary, attr, out);
}